// round 13
// baseline (speedup 1.0000x reference)
#include <cuda_runtime.h>
#include <math.h>
#include <stdint.h>
#include <limits.h>

#define BATCH 4
#define SEQ   4096
#define DIM   256
#define TOPK  32
#define ROWS  (BATCH*SEQ)
#define BK    8
#define QS    20.0f          // int8 quant scale

#define QT    256            // sgemm8: q-rows per CTA
#define KT    128            // sgemm8: k-cols per CTA

#define FULLM 0xffffffffu

// ---------------- device scratch (allocation-free contract) ----------------
__device__ float    g_q[ROWS*DIM];
__device__ float    g_k[ROWS*DIM];
__device__ float    g_v[ROWS*DIM];
__device__ uint32_t g_q8[ROWS*(DIM/4)];   // packed int8 (signed bytes)
__device__ uint32_t g_k8[ROWS*(DIM/4)];
__device__ short    g_ss[(size_t)BATCH*SEQ*SEQ];   // 134 MB int16 scores

__device__ __forceinline__ uint32_t pack4(float a, float b, float c, float d)
{
    int ia = __float2int_rn(fminf(fmaxf(a*QS, -127.f), 127.f));
    int ib = __float2int_rn(fminf(fmaxf(b*QS, -127.f), 127.f));
    int ic = __float2int_rn(fminf(fmaxf(c*QS, -127.f), 127.f));
    int id = __float2int_rn(fminf(fmaxf(d*QS, -127.f), 127.f));
    return (uint32_t)(ia & 0xff) | ((uint32_t)(ib & 0xff) << 8)
         | ((uint32_t)(ic & 0xff) << 16) | ((uint32_t)(id & 0xff) << 24);
}

// ---------------------------------------------------------------------------
// Kernel 1: fused QKV projection (R8-validated pipeline) + int8 quant of q,k.
// ---------------------------------------------------------------------------
__global__ __launch_bounds__(256, 2)
void qkv_kernel(const float* __restrict__ x,
                const float* __restrict__ Wq, const float* __restrict__ bq,
                const float* __restrict__ Wk, const float* __restrict__ bk,
                const float* __restrict__ Wv, const float* __restrict__ bv)
{
    __shared__ float As[2][BK*128];
    __shared__ float Bs[2][BK*128];

    const int which = blockIdx.z;
    const float* W    = (which==0) ? Wq : (which==1) ? Wk : Wv;
    const float* bias = (which==0) ? bq : (which==1) ? bk : bv;
    float* outp       = (which==0) ? g_q : (which==1) ? g_k : g_v;

    const int tid = threadIdx.x;
    const int tx = tid & 15, ty = tid >> 4;
    const int row0 = blockIdx.x * 128;
    const int col0 = blockIdx.y * 128;

    float acc[8][8];
    #pragma unroll
    for (int i = 0; i < 8; i++)
        #pragma unroll
        for (int j = 0; j < 8; j++) acc[i][j] = 0.f;

    const int amm = tid >> 1;
    const int akk = (tid & 1) * 4;
    const int bkk = tid >> 5;
    const int bnn = (tid & 31) * 4;

    const int NST = DIM / BK;
    float4 rA, rB;

    rA = *(const float4*)&x[(size_t)(row0 + amm)*DIM + akk];
    rB = *(const float4*)&W[(size_t)bkk*DIM + col0 + bnn];
    As[0][(akk+0)*128 + amm] = rA.x;
    As[0][(akk+1)*128 + amm] = rA.y;
    As[0][(akk+2)*128 + amm] = rA.z;
    As[0][(akk+3)*128 + amm] = rA.w;
    *(float4*)&Bs[0][bkk*128 + bnn] = rB;
    __syncthreads();

    for (int s = 0; s < NST; s++) {
        if (s + 1 < NST) {
            const int k0 = (s+1) * BK;
            rA = *(const float4*)&x[(size_t)(row0 + amm)*DIM + k0 + akk];
            rB = *(const float4*)&W[(size_t)(k0 + bkk)*DIM + col0 + bnn];
        }
        const float* Ac = As[s & 1];
        const float* Bc = Bs[s & 1];
        #pragma unroll
        for (int kk = 0; kk < BK; kk++) {
            float a[8], b[8];
            *(float4*)&a[0] = *(const float4*)&Ac[kk*128 + ty*8];
            *(float4*)&a[4] = *(const float4*)&Ac[kk*128 + ty*8 + 4];
            *(float4*)&b[0] = *(const float4*)&Bc[kk*128 + tx*8];
            *(float4*)&b[4] = *(const float4*)&Bc[kk*128 + tx*8 + 4];
            #pragma unroll
            for (int i = 0; i < 8; i++)
                #pragma unroll
                for (int j = 0; j < 8; j++)
                    acc[i][j] = fmaf(a[i], b[j], acc[i][j]);
        }
        if (s + 1 < NST) {
            float* An = As[(s+1) & 1];
            An[(akk+0)*128 + amm] = rA.x;
            An[(akk+1)*128 + amm] = rA.y;
            An[(akk+2)*128 + amm] = rA.z;
            An[(akk+3)*128 + amm] = rA.w;
            *(float4*)&Bs[(s+1) & 1][bkk*128 + bnn] = rB;
            __syncthreads();
        }
    }

    uint32_t* o8 = (which==0) ? g_q8 : g_k8;
    #pragma unroll
    for (int i = 0; i < 8; i++) {
        const int r = row0 + ty*8 + i;
        float v[8];
        #pragma unroll
        for (int j = 0; j < 8; j++) v[j] = acc[i][j] + bias[col0 + tx*8 + j];
        *(float4*)&outp[(size_t)r*DIM + col0 + tx*8]     = *(float4*)&v[0];
        *(float4*)&outp[(size_t)r*DIM + col0 + tx*8 + 4] = *(float4*)&v[4];
        if (which < 2) {
            uint2 pk;
            pk.x = pack4(v[0], v[1], v[2], v[3]);
            pk.y = pack4(v[4], v[5], v[6], v[7]);
            *(uint2*)&o8[(size_t)r*(DIM/4) + col0/4 + tx*2] = pk;
        }
    }
}

// ---------------------------------------------------------------------------
// Kernel 2: int8 score GEMM via dp4a — full-K SMEM-resident tiles, barrier-
// free mainloop. Tile 256q x 128k, 512 threads, 96KB dynamic smem, 1 CTA/SM.
// grid = (32 k-tiles, 16 q-tiles, 4 batches).
// ---------------------------------------------------------------------------
__global__ __launch_bounds__(512, 1)
void sgemm8_kernel()
{
    extern __shared__ int smx[];
    int* As8 = smx;                 // [64][QT]  64 KB, [c][row]
    int* Bs8 = smx + 64*QT;         // [64][KT]  32 KB, [c][row]

    const int tid = threadIdx.x;
    const int tx = tid & 15, ty = tid >> 4;   // ty 0..31
    const int k0t = blockIdx.x * KT;
    const int q0t = blockIdx.y * QT;
    const int b   = blockIdx.z;
    const uint32_t* q8 = g_q8 + (size_t)b*SEQ*(DIM/4);
    const uint32_t* k8 = g_k8 + (size_t)b*SEQ*(DIM/4);

    // ---- load full tiles (2-way-conflict STS pattern, R12-validated) ----
    {
        const int amm = tid >> 1;          // 0..255
        const int au  = (tid & 1) * 2;
        const int bmm = tid >> 2;          // 0..127
        const int bu  = tid & 3;
        #pragma unroll
        for (int s = 0; s < 16; s++) {
            uint2 ua = *(const uint2*)&q8[(size_t)(q0t + amm)*64 + s*4 + au];
            As8[(s*4 + au + 0)*QT + amm] = (int)ua.x;
            As8[(s*4 + au + 1)*QT + amm] = (int)ua.y;
            uint32_t ub = k8[(size_t)(k0t + bmm)*64 + s*4 + bu];
            Bs8[(s*4 + bu)*KT + bmm] = (int)ub;
        }
    }
    __syncthreads();

    int acc[8][8];
    #pragma unroll
    for (int i = 0; i < 8; i++)
        #pragma unroll
        for (int j = 0; j < 8; j++) acc[i][j] = 0;

    // ---- barrier-free mainloop: 64 c-slices ----
    #pragma unroll 4
    for (int c = 0; c < 64; c++) {
        int a[8], bb[8];
        *(int4*)&a[0]  = *(const int4*)&As8[c*QT + ty*8];
        *(int4*)&a[4]  = *(const int4*)&As8[c*QT + ty*8 + 4];
        *(int4*)&bb[0] = *(const int4*)&Bs8[c*KT + tx*8];
        *(int4*)&bb[4] = *(const int4*)&Bs8[c*KT + tx*8 + 4];
        #pragma unroll
        for (int i = 0; i < 8; i++)
            #pragma unroll
            for (int j = 0; j < 8; j++)
                acc[i][j] = __dp4a(a[i], bb[j], acc[i][j]);
    }

    // ---- saturating int16 store ----
    short* srow = g_ss + ((size_t)b*SEQ + q0t)*SEQ + k0t;
    #pragma unroll
    for (int i = 0; i < 8; i++) {
        uint32_t w[4];
        #pragma unroll
        for (int j2 = 0; j2 < 4; j2++) {
            int v0 = acc[i][j2*2+0], v1 = acc[i][j2*2+1];
            v0 = v0 > 32767 ? 32767 : (v0 < -32768 ? -32768 : v0);
            v1 = v1 > 32767 ? 32767 : (v1 < -32768 ? -32768 : v1);
            w[j2] = (uint32_t)(v0 & 0xffff) | ((uint32_t)v1 << 16);
        }
        *(uint4*)&srow[(size_t)(ty*8 + i)*SEQ + tx*8] = *(uint4*)w;
    }
}

// ---------------------------------------------------------------------------
// Kernel 3: warp-per-query int16 top-32 (ballot shift-insert) + exact fp32
// rescore + softmax + AV gather. (R12-validated — untouched.)
// ---------------------------------------------------------------------------
__global__ __launch_bounds__(256)
void select_kernel(float* __restrict__ out)
{
    const int lane = threadIdx.x & 31;
    const int gq   = blockIdx.x * 8 + (threadIdx.x >> 5);
    const int b    = gq >> 12;
    const int q    = gq & (SEQ-1);

    int myval = INT_MIN;
    int myidx = 0;

    const uint4* srow = (const uint4*)(g_ss + ((size_t)b*SEQ + q)*SEQ);

    #pragma unroll 1
    for (int i = 0; i < SEQ/256; i++) {
        uint4 u = srow[i*32 + lane];
        int sv[8];
        sv[0] = (int)(short)(u.x);  sv[1] = (int)(short)(u.x >> 16);
        sv[2] = (int)(short)(u.y);  sv[3] = (int)(short)(u.y >> 16);
        sv[4] = (int)(short)(u.z);  sv[5] = (int)(short)(u.z >> 16);
        sv[6] = (int)(short)(u.w);  sv[7] = (int)(short)(u.w >> 16);
        int thr = __shfl_sync(FULLM, myval, 31);
        bool cand = false;
        #pragma unroll
        for (int t = 0; t < 8; t++) cand |= (sv[t] > thr);
        if (__any_sync(FULLM, cand)) {
            #pragma unroll
            for (int t = 0; t < 8; t++) {
                int v = sv[t];
                thr = __shfl_sync(FULLM, myval, 31);
                unsigned cm = __ballot_sync(FULLM, v > thr);
                while (cm) {
                    int src = __ffs(cm) - 1;
                    cm &= cm - 1;
                    int bv   = __shfl_sync(FULLM, v, src);
                    int bidx = i*256 + src*8 + t;
                    bool gt = bv > myval;
                    unsigned bm = __ballot_sync(FULLM, gt);
                    int upv = __shfl_up_sync(FULLM, myval, 1);
                    int upi = __shfl_up_sync(FULLM, myidx, 1);
                    if (bm) {
                        int p = __ffs(bm) - 1;
                        if (gt) {
                            myval = (lane == p) ? bv : upv;
                            myidx = (lane == p) ? bidx : upi;
                        }
                    }
                }
            }
        }
    }

    // ---- exact fp32 rescore of the 32 selected keys ----
    const float4* qr = (const float4*)(g_q + ((size_t)b*SEQ + q)*DIM);
    float4 q0v = qr[lane*2], q1v = qr[lane*2 + 1];
    float myex = 0.f;
    #pragma unroll 4
    for (int j = 0; j < TOPK; j++) {
        int ij = __shfl_sync(FULLM, myidx, j);
        const float4* kr = (const float4*)(g_k + ((size_t)b*SEQ + ij)*DIM);
        float4 k0v = kr[lane*2], k1v = kr[lane*2 + 1];
        float d = q0v.x*k0v.x;
        d = fmaf(q0v.y, k0v.y, d);
        d = fmaf(q0v.z, k0v.z, d);
        d = fmaf(q0v.w, k0v.w, d);
        d = fmaf(q1v.x, k1v.x, d);
        d = fmaf(q1v.y, k1v.y, d);
        d = fmaf(q1v.z, k1v.z, d);
        d = fmaf(q1v.w, k1v.w, d);
        #pragma unroll
        for (int o = 16; o; o >>= 1) d += __shfl_xor_sync(FULLM, d, o);
        if (lane == j) myex = d;
    }

    float mx = myex;
    #pragma unroll
    for (int o = 16; o; o >>= 1) mx = fmaxf(mx, __shfl_xor_sync(FULLM, mx, o));
    float e = expf(myex - mx);
    float ssum = e;
    #pragma unroll
    for (int o = 16; o; o >>= 1) ssum += __shfl_xor_sync(FULLM, ssum, o);
    float p = e / ssum;

    const float4* vb = (const float4*)(g_v + (size_t)b*SEQ*DIM);
    float4 a0 = make_float4(0.f,0.f,0.f,0.f);
    float4 a1 = make_float4(0.f,0.f,0.f,0.f);
    #pragma unroll 4
    for (int j = 0; j < TOPK; j++) {
        float pj = __shfl_sync(FULLM, p, j);
        int   ij = __shfl_sync(FULLM, myidx, j);
        float4 v0 = vb[(size_t)ij*64 + lane*2];
        float4 v1 = vb[(size_t)ij*64 + lane*2 + 1];
        a0.x = fmaf(pj, v0.x, a0.x);
        a0.y = fmaf(pj, v0.y, a0.y);
        a0.z = fmaf(pj, v0.z, a0.z);
        a0.w = fmaf(pj, v0.w, a0.w);
        a1.x = fmaf(pj, v1.x, a1.x);
        a1.y = fmaf(pj, v1.y, a1.y);
        a1.z = fmaf(pj, v1.z, a1.z);
        a1.w = fmaf(pj, v1.w, a1.w);
    }
    float4* ob = (float4*)(out + ((size_t)b*SEQ + q)*DIM);
    ob[lane*2]     = a0;
    ob[lane*2 + 1] = a1;
}

static const int SG8_SMEM = (64*QT + 64*KT) * (int)sizeof(int);   // 98,304 B

extern "C" void kernel_launch(void* const* d_in, const int* in_sizes, int n_in,
                              void* d_out, int out_size)
{
    const float* x  = (const float*)d_in[0];
    const float* Wq = (const float*)d_in[1];
    const float* bq = (const float*)d_in[2];
    const float* Wk = (const float*)d_in[3];
    const float* bk = (const float*)d_in[4];
    const float* Wv = (const float*)d_in[5];
    const float* bv = (const float*)d_in[6];
    float* out = (float*)d_out;

    cudaFuncSetAttribute(sgemm8_kernel,
                         cudaFuncAttributeMaxDynamicSharedMemorySize, SG8_SMEM);

    dim3 g1(ROWS/128, DIM/128, 3);
    qkv_kernel<<<g1, 256>>>(x, Wq, bq, Wk, bk, Wv, bv);

    dim3 g2(SEQ/KT, SEQ/QT, BATCH);
    sgemm8_kernel<<<g2, 512, SG8_SMEM>>>();

    select_kernel<<<(BATCH*SEQ)/8, 256>>>(out);
}

// round 14
// speedup vs baseline: 1.0517x; 1.0517x over previous
#include <cuda_runtime.h>
#include <math.h>
#include <stdint.h>
#include <limits.h>

#define BATCH 4
#define SEQ   4096
#define DIM   256
#define TOPK  32
#define ROWS  (BATCH*SEQ)
#define BK    8
#define QS    20.0f          // int8 quant scale

#define FULLM 0xffffffffu

// ---------------- device scratch (allocation-free contract) ----------------
__device__ float    g_q[ROWS*DIM];
__device__ float    g_k[ROWS*DIM];
__device__ float    g_v[ROWS*DIM];
__device__ uint32_t g_q8[ROWS*(DIM/4)];   // packed int8 (signed bytes)
__device__ uint32_t g_k8[ROWS*(DIM/4)];
__device__ short    g_ss[(size_t)BATCH*SEQ*SEQ];   // 134 MB int16 scores

__device__ __forceinline__ uint32_t pack4(float a, float b, float c, float d)
{
    int ia = __float2int_rn(fminf(fmaxf(a*QS, -127.f), 127.f));
    int ib = __float2int_rn(fminf(fmaxf(b*QS, -127.f), 127.f));
    int ic = __float2int_rn(fminf(fmaxf(c*QS, -127.f), 127.f));
    int id = __float2int_rn(fminf(fmaxf(d*QS, -127.f), 127.f));
    return (uint32_t)(ia & 0xff) | ((uint32_t)(ib & 0xff) << 8)
         | ((uint32_t)(ic & 0xff) << 16) | ((uint32_t)(id & 0xff) << 24);
}

// ---------------------------------------------------------------------------
// Kernel 1: fused QKV projection (R8-validated pipeline, at fp32 pipe floor)
// + int8 quant of q,k.
// ---------------------------------------------------------------------------
__global__ __launch_bounds__(256, 2)
void qkv_kernel(const float* __restrict__ x,
                const float* __restrict__ Wq, const float* __restrict__ bq,
                const float* __restrict__ Wk, const float* __restrict__ bk,
                const float* __restrict__ Wv, const float* __restrict__ bv)
{
    __shared__ float As[2][BK*128];
    __shared__ float Bs[2][BK*128];

    const int which = blockIdx.z;
    const float* W    = (which==0) ? Wq : (which==1) ? Wk : Wv;
    const float* bias = (which==0) ? bq : (which==1) ? bk : bv;
    float* outp       = (which==0) ? g_q : (which==1) ? g_k : g_v;

    const int tid = threadIdx.x;
    const int tx = tid & 15, ty = tid >> 4;
    const int row0 = blockIdx.x * 128;
    const int col0 = blockIdx.y * 128;

    float acc[8][8];
    #pragma unroll
    for (int i = 0; i < 8; i++)
        #pragma unroll
        for (int j = 0; j < 8; j++) acc[i][j] = 0.f;

    const int amm = tid >> 1;
    const int akk = (tid & 1) * 4;
    const int bkk = tid >> 5;
    const int bnn = (tid & 31) * 4;

    const int NST = DIM / BK;
    float4 rA, rB;

    rA = *(const float4*)&x[(size_t)(row0 + amm)*DIM + akk];
    rB = *(const float4*)&W[(size_t)bkk*DIM + col0 + bnn];
    As[0][(akk+0)*128 + amm] = rA.x;
    As[0][(akk+1)*128 + amm] = rA.y;
    As[0][(akk+2)*128 + amm] = rA.z;
    As[0][(akk+3)*128 + amm] = rA.w;
    *(float4*)&Bs[0][bkk*128 + bnn] = rB;
    __syncthreads();

    for (int s = 0; s < NST; s++) {
        if (s + 1 < NST) {
            const int k0 = (s+1) * BK;
            rA = *(const float4*)&x[(size_t)(row0 + amm)*DIM + k0 + akk];
            rB = *(const float4*)&W[(size_t)(k0 + bkk)*DIM + col0 + bnn];
        }
        const float* Ac = As[s & 1];
        const float* Bc = Bs[s & 1];
        #pragma unroll
        for (int kk = 0; kk < BK; kk++) {
            float a[8], b[8];
            *(float4*)&a[0] = *(const float4*)&Ac[kk*128 + ty*8];
            *(float4*)&a[4] = *(const float4*)&Ac[kk*128 + ty*8 + 4];
            *(float4*)&b[0] = *(const float4*)&Bc[kk*128 + tx*8];
            *(float4*)&b[4] = *(const float4*)&Bc[kk*128 + tx*8 + 4];
            #pragma unroll
            for (int i = 0; i < 8; i++)
                #pragma unroll
                for (int j = 0; j < 8; j++)
                    acc[i][j] = fmaf(a[i], b[j], acc[i][j]);
        }
        if (s + 1 < NST) {
            float* An = As[(s+1) & 1];
            An[(akk+0)*128 + amm] = rA.x;
            An[(akk+1)*128 + amm] = rA.y;
            An[(akk+2)*128 + amm] = rA.z;
            An[(akk+3)*128 + amm] = rA.w;
            *(float4*)&Bs[(s+1) & 1][bkk*128 + bnn] = rB;
            __syncthreads();
        }
    }

    uint32_t* o8 = (which==0) ? g_q8 : g_k8;
    #pragma unroll
    for (int i = 0; i < 8; i++) {
        const int r = row0 + ty*8 + i;
        float v[8];
        #pragma unroll
        for (int j = 0; j < 8; j++) v[j] = acc[i][j] + bias[col0 + tx*8 + j];
        *(float4*)&outp[(size_t)r*DIM + col0 + tx*8]     = *(float4*)&v[0];
        *(float4*)&outp[(size_t)r*DIM + col0 + tx*8 + 4] = *(float4*)&v[4];
        if (which < 2) {
            uint2 pk;
            pk.x = pack4(v[0], v[1], v[2], v[3]);
            pk.y = pack4(v[4], v[5], v[6], v[7]);
            *(uint2*)&o8[(size_t)r*(DIM/4) + col0/4 + tx*2] = pk;
        }
    }
}

// ---------------------------------------------------------------------------
// Kernel 2: int8 score GEMM via dp4a, double-buffered, 8 stages of 8 u32
// (uint4 prefetch, 8 barriers). Tile 128q x 128k, 256 threads, 2 CTAs/SM.
// grid = (32 k-tiles, 32 q-tiles, 4 batches).
// ---------------------------------------------------------------------------
__global__ __launch_bounds__(256, 2)
void sgemm8_kernel()
{
    __shared__ int As8[2][8*128];   // [buf][c][row]  4KB each
    __shared__ int Bs8[2][8*128];

    const int tid = threadIdx.x;
    const int tx = tid & 15, ty = tid >> 4;
    const int k0t = blockIdx.x * 128;
    const int q0t = blockIdx.y * 128;
    const int b   = blockIdx.z;
    const uint32_t* q8 = g_q8 + (size_t)b*SEQ*(DIM/4);
    const uint32_t* k8 = g_k8 + (size_t)b*SEQ*(DIM/4);

    int acc[8][8];
    #pragma unroll
    for (int i = 0; i < 8; i++)
        #pragma unroll
        for (int j = 0; j < 8; j++) acc[i][j] = 0;

    const int amm = tid >> 1;          // 0..127
    const int au  = (tid & 1) * 4;     // u32 offset within stage (uint4)

    const int NST = 8;                 // 8 stages x 8 u32 = K 256
    uint4 rA, rB;

    rA = *(const uint4*)&q8[(size_t)(q0t + amm)*(DIM/4) + au];
    rB = *(const uint4*)&k8[(size_t)(k0t + amm)*(DIM/4) + au];
    As8[0][(au+0)*128 + amm] = (int)rA.x;
    As8[0][(au+1)*128 + amm] = (int)rA.y;
    As8[0][(au+2)*128 + amm] = (int)rA.z;
    As8[0][(au+3)*128 + amm] = (int)rA.w;
    Bs8[0][(au+0)*128 + amm] = (int)rB.x;
    Bs8[0][(au+1)*128 + amm] = (int)rB.y;
    Bs8[0][(au+2)*128 + amm] = (int)rB.z;
    Bs8[0][(au+3)*128 + amm] = (int)rB.w;
    __syncthreads();

    for (int s = 0; s < NST; s++) {
        if (s + 1 < NST) {
            rA = *(const uint4*)&q8[(size_t)(q0t + amm)*(DIM/4) + (s+1)*8 + au];
            rB = *(const uint4*)&k8[(size_t)(k0t + amm)*(DIM/4) + (s+1)*8 + au];
        }
        const int* Ac = As8[s & 1];
        const int* Bc = Bs8[s & 1];
        #pragma unroll
        for (int pk = 0; pk < 8; pk++) {
            int a[8], bb[8];
            *(int4*)&a[0]  = *(const int4*)&Ac[pk*128 + ty*8];
            *(int4*)&a[4]  = *(const int4*)&Ac[pk*128 + ty*8 + 4];
            *(int4*)&bb[0] = *(const int4*)&Bc[pk*128 + tx*8];
            *(int4*)&bb[4] = *(const int4*)&Bc[pk*128 + tx*8 + 4];
            #pragma unroll
            for (int i = 0; i < 8; i++)
                #pragma unroll
                for (int j = 0; j < 8; j++)
                    acc[i][j] = __dp4a(a[i], bb[j], acc[i][j]);
        }
        if (s + 1 < NST) {
            int* An = As8[(s+1) & 1];
            int* Bn = Bs8[(s+1) & 1];
            An[(au+0)*128 + amm] = (int)rA.x;
            An[(au+1)*128 + amm] = (int)rA.y;
            An[(au+2)*128 + amm] = (int)rA.z;
            An[(au+3)*128 + amm] = (int)rA.w;
            Bn[(au+0)*128 + amm] = (int)rB.x;
            Bn[(au+1)*128 + amm] = (int)rB.y;
            Bn[(au+2)*128 + amm] = (int)rB.z;
            Bn[(au+3)*128 + amm] = (int)rB.w;
            __syncthreads();
        }
    }

    // saturating int16 store
    short* srow = g_ss + ((size_t)b*SEQ + q0t)*SEQ + k0t;
    #pragma unroll
    for (int i = 0; i < 8; i++) {
        uint32_t w[4];
        #pragma unroll
        for (int j2 = 0; j2 < 4; j2++) {
            int v0 = acc[i][j2*2+0], v1 = acc[i][j2*2+1];
            v0 = v0 > 32767 ? 32767 : (v0 < -32768 ? -32768 : v0);
            v1 = v1 > 32767 ? 32767 : (v1 < -32768 ? -32768 : v1);
            w[j2] = (uint32_t)(v0 & 0xffff) | ((uint32_t)v1 << 16);
        }
        *(uint4*)&srow[(size_t)(ty*8 + i)*SEQ + tx*8] = *(uint4*)w;
    }
}

// ---------------------------------------------------------------------------
// Kernel 3: warp-per-query int16 top-32 (ballot shift-insert) + exact fp32
// rescore + softmax + AV gather. (R12-validated; score reads now streaming.)
// ---------------------------------------------------------------------------
__global__ __launch_bounds__(256)
void select_kernel(float* __restrict__ out)
{
    const int lane = threadIdx.x & 31;
    const int gq   = blockIdx.x * 8 + (threadIdx.x >> 5);
    const int b    = gq >> 12;
    const int q    = gq & (SEQ-1);

    int myval = INT_MIN;
    int myidx = 0;

    const uint4* srow = (const uint4*)(g_ss + ((size_t)b*SEQ + q)*SEQ);

    #pragma unroll 1
    for (int i = 0; i < SEQ/256; i++) {
        uint4 u = __ldcs(&srow[i*32 + lane]);   // streaming: no-reuse data
        int sv[8];
        sv[0] = (int)(short)(u.x);  sv[1] = (int)(short)(u.x >> 16);
        sv[2] = (int)(short)(u.y);  sv[3] = (int)(short)(u.y >> 16);
        sv[4] = (int)(short)(u.z);  sv[5] = (int)(short)(u.z >> 16);
        sv[6] = (int)(short)(u.w);  sv[7] = (int)(short)(u.w >> 16);
        int thr = __shfl_sync(FULLM, myval, 31);
        bool cand = false;
        #pragma unroll
        for (int t = 0; t < 8; t++) cand |= (sv[t] > thr);
        if (__any_sync(FULLM, cand)) {
            #pragma unroll
            for (int t = 0; t < 8; t++) {
                int v = sv[t];
                thr = __shfl_sync(FULLM, myval, 31);
                unsigned cm = __ballot_sync(FULLM, v > thr);
                while (cm) {
                    int src = __ffs(cm) - 1;
                    cm &= cm - 1;
                    int bv   = __shfl_sync(FULLM, v, src);
                    int bidx = i*256 + src*8 + t;
                    bool gt = bv > myval;
                    unsigned bm = __ballot_sync(FULLM, gt);
                    int upv = __shfl_up_sync(FULLM, myval, 1);
                    int upi = __shfl_up_sync(FULLM, myidx, 1);
                    if (bm) {
                        int p = __ffs(bm) - 1;
                        if (gt) {
                            myval = (lane == p) ? bv : upv;
                            myidx = (lane == p) ? bidx : upi;
                        }
                    }
                }
            }
        }
    }

    // ---- exact fp32 rescore of the 32 selected keys ----
    const float4* qr = (const float4*)(g_q + ((size_t)b*SEQ + q)*DIM);
    float4 q0v = qr[lane*2], q1v = qr[lane*2 + 1];
    float myex = 0.f;
    #pragma unroll 4
    for (int j = 0; j < TOPK; j++) {
        int ij = __shfl_sync(FULLM, myidx, j);
        const float4* kr = (const float4*)(g_k + ((size_t)b*SEQ + ij)*DIM);
        float4 k0v = kr[lane*2], k1v = kr[lane*2 + 1];
        float d = q0v.x*k0v.x;
        d = fmaf(q0v.y, k0v.y, d);
        d = fmaf(q0v.z, k0v.z, d);
        d = fmaf(q0v.w, k0v.w, d);
        d = fmaf(q1v.x, k1v.x, d);
        d = fmaf(q1v.y, k1v.y, d);
        d = fmaf(q1v.z, k1v.z, d);
        d = fmaf(q1v.w, k1v.w, d);
        #pragma unroll
        for (int o = 16; o; o >>= 1) d += __shfl_xor_sync(FULLM, d, o);
        if (lane == j) myex = d;
    }

    float mx = myex;
    #pragma unroll
    for (int o = 16; o; o >>= 1) mx = fmaxf(mx, __shfl_xor_sync(FULLM, mx, o));
    float e = expf(myex - mx);
    float ssum = e;
    #pragma unroll
    for (int o = 16; o; o >>= 1) ssum += __shfl_xor_sync(FULLM, ssum, o);
    float p = e / ssum;

    const float4* vb = (const float4*)(g_v + (size_t)b*SEQ*DIM);
    float4 a0 = make_float4(0.f,0.f,0.f,0.f);
    float4 a1 = make_float4(0.f,0.f,0.f,0.f);
    #pragma unroll 4
    for (int j = 0; j < TOPK; j++) {
        float pj = __shfl_sync(FULLM, p, j);
        int   ij = __shfl_sync(FULLM, myidx, j);
        float4 v0 = vb[(size_t)ij*64 + lane*2];
        float4 v1 = vb[(size_t)ij*64 + lane*2 + 1];
        a0.x = fmaf(pj, v0.x, a0.x);
        a0.y = fmaf(pj, v0.y, a0.y);
        a0.z = fmaf(pj, v0.z, a0.z);
        a0.w = fmaf(pj, v0.w, a0.w);
        a1.x = fmaf(pj, v1.x, a1.x);
        a1.y = fmaf(pj, v1.y, a1.y);
        a1.z = fmaf(pj, v1.z, a1.z);
        a1.w = fmaf(pj, v1.w, a1.w);
    }
    float4* ob = (float4*)(out + ((size_t)b*SEQ + q)*DIM);
    ob[lane*2]     = a0;
    ob[lane*2 + 1] = a1;
}

extern "C" void kernel_launch(void* const* d_in, const int* in_sizes, int n_in,
                              void* d_out, int out_size)
{
    const float* x  = (const float*)d_in[0];
    const float* Wq = (const float*)d_in[1];
    const float* bq = (const float*)d_in[2];
    const float* Wk = (const float*)d_in[3];
    const float* bk = (const float*)d_in[4];
    const float* Wv = (const float*)d_in[5];
    const float* bv = (const float*)d_in[6];
    float* out = (float*)d_out;

    dim3 g1(ROWS/128, DIM/128, 3);
    qkv_kernel<<<g1, 256>>>(x, Wq, bq, Wk, bk, Wv, bv);

    dim3 g2(SEQ/128, SEQ/128, BATCH);
    sgemm8_kernel<<<g2, 256>>>();

    select_kernel<<<(BATCH*SEQ)/8, 256>>>(out);
}

// round 15
// speedup vs baseline: 1.1664x; 1.1090x over previous
#include <cuda_runtime.h>
#include <math.h>
#include <stdint.h>
#include <limits.h>

#define BATCH 4
#define SEQ   4096
#define DIM   256
#define TOPK  32
#define ROWS  (BATCH*SEQ)
#define BK    8
#define QS    20.0f          // int8 quant scale

#define FULLM 0xffffffffu

// ---------------- device scratch (allocation-free contract) ----------------
__device__ float    g_q[ROWS*DIM];
__device__ float    g_k[ROWS*DIM];
__device__ float    g_v[ROWS*DIM];
__device__ uint32_t g_q8[ROWS*(DIM/4)];   // packed int8 (signed bytes)
__device__ uint32_t g_k8[ROWS*(DIM/4)];
__device__ short    g_ss[(size_t)BATCH*SEQ*SEQ];   // 134 MB int16 scores

__device__ __forceinline__ uint32_t pack4(float a, float b, float c, float d)
{
    int ia = __float2int_rn(fminf(fmaxf(a*QS, -127.f), 127.f));
    int ib = __float2int_rn(fminf(fmaxf(b*QS, -127.f), 127.f));
    int ic = __float2int_rn(fminf(fmaxf(c*QS, -127.f), 127.f));
    int id = __float2int_rn(fminf(fmaxf(d*QS, -127.f), 127.f));
    return (uint32_t)(ia & 0xff) | ((uint32_t)(ib & 0xff) << 8)
         | ((uint32_t)(ic & 0xff) << 16) | ((uint32_t)(id & 0xff) << 24);
}

// ---------------------------------------------------------------------------
// Kernel 1: q,k projections only (z=2), R8 pipeline + int8 quant.
// ---------------------------------------------------------------------------
__global__ __launch_bounds__(256, 2)
void qkv_kernel(const float* __restrict__ x,
                const float* __restrict__ Wq, const float* __restrict__ bq,
                const float* __restrict__ Wk, const float* __restrict__ bk)
{
    __shared__ float As[2][BK*128];
    __shared__ float Bs[2][BK*128];

    const int which = blockIdx.z;             // 0=q, 1=k
    const float* W    = (which==0) ? Wq : Wk;
    const float* bias = (which==0) ? bq : bk;
    float* outp       = (which==0) ? g_q : g_k;

    const int tid = threadIdx.x;
    const int tx = tid & 15, ty = tid >> 4;
    const int row0 = blockIdx.x * 128;
    const int col0 = blockIdx.y * 128;

    float acc[8][8];
    #pragma unroll
    for (int i = 0; i < 8; i++)
        #pragma unroll
        for (int j = 0; j < 8; j++) acc[i][j] = 0.f;

    const int amm = tid >> 1;
    const int akk = (tid & 1) * 4;
    const int bkk = tid >> 5;
    const int bnn = (tid & 31) * 4;

    const int NST = DIM / BK;
    float4 rA, rB;

    rA = *(const float4*)&x[(size_t)(row0 + amm)*DIM + akk];
    rB = *(const float4*)&W[(size_t)bkk*DIM + col0 + bnn];
    As[0][(akk+0)*128 + amm] = rA.x;
    As[0][(akk+1)*128 + amm] = rA.y;
    As[0][(akk+2)*128 + amm] = rA.z;
    As[0][(akk+3)*128 + amm] = rA.w;
    *(float4*)&Bs[0][bkk*128 + bnn] = rB;
    __syncthreads();

    for (int s = 0; s < NST; s++) {
        if (s + 1 < NST) {
            const int k0 = (s+1) * BK;
            rA = *(const float4*)&x[(size_t)(row0 + amm)*DIM + k0 + akk];
            rB = *(const float4*)&W[(size_t)(k0 + bkk)*DIM + col0 + bnn];
        }
        const float* Ac = As[s & 1];
        const float* Bc = Bs[s & 1];
        #pragma unroll
        for (int kk = 0; kk < BK; kk++) {
            float a[8], b[8];
            *(float4*)&a[0] = *(const float4*)&Ac[kk*128 + ty*8];
            *(float4*)&a[4] = *(const float4*)&Ac[kk*128 + ty*8 + 4];
            *(float4*)&b[0] = *(const float4*)&Bc[kk*128 + tx*8];
            *(float4*)&b[4] = *(const float4*)&Bc[kk*128 + tx*8 + 4];
            #pragma unroll
            for (int i = 0; i < 8; i++)
                #pragma unroll
                for (int j = 0; j < 8; j++)
                    acc[i][j] = fmaf(a[i], b[j], acc[i][j]);
        }
        if (s + 1 < NST) {
            float* An = As[(s+1) & 1];
            An[(akk+0)*128 + amm] = rA.x;
            An[(akk+1)*128 + amm] = rA.y;
            An[(akk+2)*128 + amm] = rA.z;
            An[(akk+3)*128 + amm] = rA.w;
            *(float4*)&Bs[(s+1) & 1][bkk*128 + bnn] = rB;
            __syncthreads();
        }
    }

    uint32_t* o8 = (which==0) ? g_q8 : g_k8;
    #pragma unroll
    for (int i = 0; i < 8; i++) {
        const int r = row0 + ty*8 + i;
        float v[8];
        #pragma unroll
        for (int j = 0; j < 8; j++) v[j] = acc[i][j] + bias[col0 + tx*8 + j];
        *(float4*)&outp[(size_t)r*DIM + col0 + tx*8]     = *(float4*)&v[0];
        *(float4*)&outp[(size_t)r*DIM + col0 + tx*8 + 4] = *(float4*)&v[4];
        uint2 pk;
        pk.x = pack4(v[0], v[1], v[2], v[3]);
        pk.y = pack4(v[4], v[5], v[6], v[7]);
        *(uint2*)&o8[(size_t)r*(DIM/4) + col0/4 + tx*2] = pk;
    }
}

// ---------------------------------------------------------------------------
// Kernel 2: z==0 -> v projection (fp32, fills idle FMA pipe while dp4a runs);
// z 1..4 -> int8 score GEMM via dp4a (R14 structure, batch b = z-1).
// ---------------------------------------------------------------------------
__global__ __launch_bounds__(256, 2)
void sgemm8_kernel(const float* __restrict__ x,
                   const float* __restrict__ Wv, const float* __restrict__ bv)
{
    __shared__ __align__(16) char smraw[16384];   // shared by both paths

    const int tid = threadIdx.x;
    const int tx = tid & 15, ty = tid >> 4;

    if (blockIdx.z == 0) {
        // ---------------- v projection path ----------------
        const int idx = blockIdx.y * 32 + blockIdx.x;
        if (idx >= (ROWS/128) * (DIM/128)) return;   // 256 live blocks
        const int row0 = (idx >> 1) * 128;
        const int col0 = (idx & 1)  * 128;

        float* As = (float*)smraw;            // [2][BK*128]
        float* Bs = (float*)smraw + 2*BK*128;

        float acc[8][8];
        #pragma unroll
        for (int i = 0; i < 8; i++)
            #pragma unroll
            for (int j = 0; j < 8; j++) acc[i][j] = 0.f;

        const int amm = tid >> 1;
        const int akk = (tid & 1) * 4;
        const int bkk = tid >> 5;
        const int bnn = (tid & 31) * 4;

        const int NST = DIM / BK;
        float4 rA, rB;

        rA = *(const float4*)&x[(size_t)(row0 + amm)*DIM + akk];
        rB = *(const float4*)&Wv[(size_t)bkk*DIM + col0 + bnn];
        As[0*BK*128 + (akk+0)*128 + amm] = rA.x;
        As[0*BK*128 + (akk+1)*128 + amm] = rA.y;
        As[0*BK*128 + (akk+2)*128 + amm] = rA.z;
        As[0*BK*128 + (akk+3)*128 + amm] = rA.w;
        *(float4*)&Bs[0*BK*128 + bkk*128 + bnn] = rB;
        __syncthreads();

        for (int s = 0; s < NST; s++) {
            if (s + 1 < NST) {
                const int k0 = (s+1) * BK;
                rA = *(const float4*)&x[(size_t)(row0 + amm)*DIM + k0 + akk];
                rB = *(const float4*)&Wv[(size_t)(k0 + bkk)*DIM + col0 + bnn];
            }
            const float* Ac = As + (s & 1)*BK*128;
            const float* Bc = Bs + (s & 1)*BK*128;
            #pragma unroll
            for (int kk = 0; kk < BK; kk++) {
                float a[8], b[8];
                *(float4*)&a[0] = *(const float4*)&Ac[kk*128 + ty*8];
                *(float4*)&a[4] = *(const float4*)&Ac[kk*128 + ty*8 + 4];
                *(float4*)&b[0] = *(const float4*)&Bc[kk*128 + tx*8];
                *(float4*)&b[4] = *(const float4*)&Bc[kk*128 + tx*8 + 4];
                #pragma unroll
                for (int i = 0; i < 8; i++)
                    #pragma unroll
                    for (int j = 0; j < 8; j++)
                        acc[i][j] = fmaf(a[i], b[j], acc[i][j]);
            }
            if (s + 1 < NST) {
                float* An = As + ((s+1) & 1)*BK*128;
                An[(akk+0)*128 + amm] = rA.x;
                An[(akk+1)*128 + amm] = rA.y;
                An[(akk+2)*128 + amm] = rA.z;
                An[(akk+3)*128 + amm] = rA.w;
                *(float4*)&Bs[((s+1) & 1)*BK*128 + bkk*128 + bnn] = rB;
                __syncthreads();
            }
        }

        #pragma unroll
        for (int i = 0; i < 8; i++) {
            const int r = row0 + ty*8 + i;
            #pragma unroll
            for (int j = 0; j < 8; j += 4) {
                const int c = col0 + tx*8 + j;
                float4 o;
                o.x = acc[i][j+0] + bv[c+0];
                o.y = acc[i][j+1] + bv[c+1];
                o.z = acc[i][j+2] + bv[c+2];
                o.w = acc[i][j+3] + bv[c+3];
                *(float4*)&g_v[(size_t)r*DIM + c] = o;
            }
        }
        return;
    }

    // ---------------- int8 score GEMM path ----------------
    int* As8 = (int*)smraw;          // [2][8*128]
    int* Bs8 = (int*)smraw + 2048;   // [2][8*128]

    const int k0t = blockIdx.x * 128;
    const int q0t = blockIdx.y * 128;
    const int b   = blockIdx.z - 1;
    const uint32_t* q8 = g_q8 + (size_t)b*SEQ*(DIM/4);
    const uint32_t* k8 = g_k8 + (size_t)b*SEQ*(DIM/4);

    int acc[8][8];
    #pragma unroll
    for (int i = 0; i < 8; i++)
        #pragma unroll
        for (int j = 0; j < 8; j++) acc[i][j] = 0;

    const int amm = tid >> 1;          // 0..127
    const int au  = (tid & 1) * 4;     // u32 offset within stage (uint4)

    const int NST = 8;                 // 8 stages x 8 u32 = K 256
    uint4 rA, rB;

    rA = *(const uint4*)&q8[(size_t)(q0t + amm)*(DIM/4) + au];
    rB = *(const uint4*)&k8[(size_t)(k0t + amm)*(DIM/4) + au];
    As8[(au+0)*128 + amm] = (int)rA.x;
    As8[(au+1)*128 + amm] = (int)rA.y;
    As8[(au+2)*128 + amm] = (int)rA.z;
    As8[(au+3)*128 + amm] = (int)rA.w;
    Bs8[(au+0)*128 + amm] = (int)rB.x;
    Bs8[(au+1)*128 + amm] = (int)rB.y;
    Bs8[(au+2)*128 + amm] = (int)rB.z;
    Bs8[(au+3)*128 + amm] = (int)rB.w;
    __syncthreads();

    for (int s = 0; s < NST; s++) {
        if (s + 1 < NST) {
            rA = *(const uint4*)&q8[(size_t)(q0t + amm)*(DIM/4) + (s+1)*8 + au];
            rB = *(const uint4*)&k8[(size_t)(k0t + amm)*(DIM/4) + (s+1)*8 + au];
        }
        const int* Ac = As8 + (s & 1)*1024;
        const int* Bc = Bs8 + (s & 1)*1024;
        #pragma unroll
        for (int pk = 0; pk < 8; pk++) {
            int a[8], bb[8];
            *(int4*)&a[0]  = *(const int4*)&Ac[pk*128 + ty*8];
            *(int4*)&a[4]  = *(const int4*)&Ac[pk*128 + ty*8 + 4];
            *(int4*)&bb[0] = *(const int4*)&Bc[pk*128 + tx*8];
            *(int4*)&bb[4] = *(const int4*)&Bc[pk*128 + tx*8 + 4];
            #pragma unroll
            for (int i = 0; i < 8; i++)
                #pragma unroll
                for (int j = 0; j < 8; j++)
                    acc[i][j] = __dp4a(a[i], bb[j], acc[i][j]);
        }
        if (s + 1 < NST) {
            int* An = As8 + ((s+1) & 1)*1024;
            int* Bn = Bs8 + ((s+1) & 1)*1024;
            An[(au+0)*128 + amm] = (int)rA.x;
            An[(au+1)*128 + amm] = (int)rA.y;
            An[(au+2)*128 + amm] = (int)rA.z;
            An[(au+3)*128 + amm] = (int)rA.w;
            Bn[(au+0)*128 + amm] = (int)rB.x;
            Bn[(au+1)*128 + amm] = (int)rB.y;
            Bn[(au+2)*128 + amm] = (int)rB.z;
            Bn[(au+3)*128 + amm] = (int)rB.w;
            __syncthreads();
        }
    }

    // saturating int16 store
    short* srow = g_ss + ((size_t)b*SEQ + q0t)*SEQ + k0t;
    #pragma unroll
    for (int i = 0; i < 8; i++) {
        uint32_t w[4];
        #pragma unroll
        for (int j2 = 0; j2 < 4; j2++) {
            int v0 = acc[i][j2*2+0], v1 = acc[i][j2*2+1];
            v0 = v0 > 32767 ? 32767 : (v0 < -32768 ? -32768 : v0);
            v1 = v1 > 32767 ? 32767 : (v1 < -32768 ? -32768 : v1);
            w[j2] = (uint32_t)(v0 & 0xffff) | ((uint32_t)v1 << 16);
        }
        *(uint4*)&srow[(size_t)(ty*8 + i)*SEQ + tx*8] = *(uint4*)w;
    }
}

// ---------------------------------------------------------------------------
// Kernel 3: warp-per-query int16 top-32 (prefetched scan, ballot shift-
// insert) + exact fp32 rescore + softmax + AV gather.
// ---------------------------------------------------------------------------
__global__ __launch_bounds__(256)
void select_kernel(float* __restrict__ out)
{
    const int lane = threadIdx.x & 31;
    const int gq   = blockIdx.x * 8 + (threadIdx.x >> 5);
    const int b    = gq >> 12;
    const int q    = gq & (SEQ-1);

    int myval = INT_MIN;
    int myidx = 0;

    const uint4* srow = (const uint4*)(g_ss + ((size_t)b*SEQ + q)*SEQ);

    uint4 u = __ldcs(&srow[lane]);     // prefetch iteration 0
    #pragma unroll 1
    for (int i = 0; i < SEQ/256; i++) {
        uint4 cur = u;
        if (i + 1 < SEQ/256)
            u = __ldcs(&srow[(i+1)*32 + lane]);   // hoisted next-iter load
        int sv[8];
        sv[0] = (int)(short)(cur.x);  sv[1] = (int)(short)(cur.x >> 16);
        sv[2] = (int)(short)(cur.y);  sv[3] = (int)(short)(cur.y >> 16);
        sv[4] = (int)(short)(cur.z);  sv[5] = (int)(short)(cur.z >> 16);
        sv[6] = (int)(short)(cur.w);  sv[7] = (int)(short)(cur.w >> 16);
        int thr = __shfl_sync(FULLM, myval, 31);
        bool cand = false;
        #pragma unroll
        for (int t = 0; t < 8; t++) cand |= (sv[t] > thr);
        if (__any_sync(FULLM, cand)) {
            #pragma unroll
            for (int t = 0; t < 8; t++) {
                int v = sv[t];
                thr = __shfl_sync(FULLM, myval, 31);
                unsigned cm = __ballot_sync(FULLM, v > thr);
                while (cm) {
                    int src = __ffs(cm) - 1;
                    cm &= cm - 1;
                    int bv   = __shfl_sync(FULLM, v, src);
                    int bidx = i*256 + src*8 + t;
                    bool gt = bv > myval;
                    unsigned bm = __ballot_sync(FULLM, gt);
                    int upv = __shfl_up_sync(FULLM, myval, 1);
                    int upi = __shfl_up_sync(FULLM, myidx, 1);
                    if (bm) {
                        int p = __ffs(bm) - 1;
                        if (gt) {
                            myval = (lane == p) ? bv : upv;
                            myidx = (lane == p) ? bidx : upi;
                        }
                    }
                }
            }
        }
    }

    // ---- exact fp32 rescore of the 32 selected keys ----
    const float4* qr = (const float4*)(g_q + ((size_t)b*SEQ + q)*DIM);
    float4 q0v = qr[lane*2], q1v = qr[lane*2 + 1];
    float myex = 0.f;
    #pragma unroll 4
    for (int j = 0; j < TOPK; j++) {
        int ij = __shfl_sync(FULLM, myidx, j);
        const float4* kr = (const float4*)(g_k + ((size_t)b*SEQ + ij)*DIM);
        float4 k0v = kr[lane*2], k1v = kr[lane*2 + 1];
        float d = q0v.x*k0v.x;
        d = fmaf(q0v.y, k0v.y, d);
        d = fmaf(q0v.z, k0v.z, d);
        d = fmaf(q0v.w, k0v.w, d);
        d = fmaf(q1v.x, k1v.x, d);
        d = fmaf(q1v.y, k1v.y, d);
        d = fmaf(q1v.z, k1v.z, d);
        d = fmaf(q1v.w, k1v.w, d);
        #pragma unroll
        for (int o = 16; o; o >>= 1) d += __shfl_xor_sync(FULLM, d, o);
        if (lane == j) myex = d;
    }

    float mx = myex;
    #pragma unroll
    for (int o = 16; o; o >>= 1) mx = fmaxf(mx, __shfl_xor_sync(FULLM, mx, o));
    float e = expf(myex - mx);
    float ssum = e;
    #pragma unroll
    for (int o = 16; o; o >>= 1) ssum += __shfl_xor_sync(FULLM, ssum, o);
    float p = e / ssum;

    const float4* vb = (const float4*)(g_v + (size_t)b*SEQ*DIM);
    float4 a0 = make_float4(0.f,0.f,0.f,0.f);
    float4 a1 = make_float4(0.f,0.f,0.f,0.f);
    #pragma unroll 4
    for (int j = 0; j < TOPK; j++) {
        float pj = __shfl_sync(FULLM, p, j);
        int   ij = __shfl_sync(FULLM, myidx, j);
        float4 v0 = vb[(size_t)ij*64 + lane*2];
        float4 v1 = vb[(size_t)ij*64 + lane*2 + 1];
        a0.x = fmaf(pj, v0.x, a0.x);
        a0.y = fmaf(pj, v0.y, a0.y);
        a0.z = fmaf(pj, v0.z, a0.z);
        a0.w = fmaf(pj, v0.w, a0.w);
        a1.x = fmaf(pj, v1.x, a1.x);
        a1.y = fmaf(pj, v1.y, a1.y);
        a1.z = fmaf(pj, v1.z, a1.z);
        a1.w = fmaf(pj, v1.w, a1.w);
    }
    float4* ob = (float4*)(out + ((size_t)b*SEQ + q)*DIM);
    ob[lane*2]     = a0;
    ob[lane*2 + 1] = a1;
}

extern "C" void kernel_launch(void* const* d_in, const int* in_sizes, int n_in,
                              void* d_out, int out_size)
{
    const float* x  = (const float*)d_in[0];
    const float* Wq = (const float*)d_in[1];
    const float* bq = (const float*)d_in[2];
    const float* Wk = (const float*)d_in[3];
    const float* bk = (const float*)d_in[4];
    const float* Wv = (const float*)d_in[5];
    const float* bv = (const float*)d_in[6];
    float* out = (float*)d_out;

    dim3 g1(ROWS/128, DIM/128, 2);            // q,k only
    qkv_kernel<<<g1, 256>>>(x, Wq, bq, Wk, bk);

    dim3 g2(SEQ/128, SEQ/128, BATCH + 1);     // z=0: vproj; z=1..4: scores
    sgemm8_kernel<<<g2, 256>>>(x, Wv, bv);

    select_kernel<<<(BATCH*SEQ)/8, 256>>>(out);
}